// round 6
// baseline (speedup 1.0000x reference)
#include <cuda_runtime.h>

#define NN 1048576
#define EE 8388608
#define GG 32768
#define PS 12   // padded row stride (9 ch + 3 pad) -> 48B, 16B-aligned
#define NITER 8
#define NB_NODE (NN / (256 * NITER))   // 512
#define NB_EDGE (EE / (256 * 2))       // 16384
#define NB_G (GG / 256)                // 128

// ---------------- device state (no allocation allowed) ----------------
__device__ __align__(16) float  g_hin[(size_t)NN * PS];
__device__ __align__(16) float  g_buf[(size_t)NN * PS];
__device__ __align__(16) float  g_vn [(size_t)GG * PS];
__device__ __align__(16) float  g_gs [(size_t)GG * PS];
// per-layer raw BN stats: sum at [c], sumsq at [18+c], 36-stride per layer
__device__ double g_stZ1[3 * 36];   // z@W1+b1, 18 ch
__device__ double g_stZ2[3 * 36];   // z2, 9 ch
__device__ double g_stV1[2 * 36];   // vn MLP hidden, 18 ch
__device__ double g_stV2[2 * 36];   // vn MLP out, 9 ch
__device__ double g_outacc[9];

// ---------------- helpers ----------------
__device__ __forceinline__ void red_add4(float* p, float a, float b, float c, float d) {
    asm volatile("red.global.add.v4.f32 [%0], {%1,%2,%3,%4};"
                 :: "l"(__cvta_generic_to_global(p)), "f"(a), "f"(b), "f"(c), "f"(d) : "memory");
}
__device__ __forceinline__ void red_add1(float* p, float a) {
    asm volatile("red.global.add.f32 [%0], %1;"
                 :: "l"(__cvta_generic_to_global(p)), "f"(a) : "memory");
}
__device__ __forceinline__ float warp_sum(float v) {
    #pragma unroll
    for (int off = 16; off > 0; off >>= 1) v += __shfl_down_sync(0xffffffffu, v, off);
    return v;
}

// warp-level segmented sum over sorted keys, then 3 vector atomics per segment head
__device__ __forceinline__ void seg_atomic9(int key, float v[9], float* dstBase) {
    int lane = threadIdx.x & 31;
    #pragma unroll
    for (int off = 1; off < 32; off <<= 1) {
        int nk = __shfl_down_sync(0xffffffffu, key, off);
        float t[9];
        #pragma unroll
        for (int k = 0; k < 9; k++) t[k] = __shfl_down_sync(0xffffffffu, v[k], off);
        if (lane + off < 32 && nk == key) {
            #pragma unroll
            for (int k = 0; k < 9; k++) v[k] += t[k];
        }
    }
    int pk = __shfl_up_sync(0xffffffffu, key, 1);
    if (lane == 0 || pk != key) {
        float* p = dstBase + (size_t)key * PS;
        red_add4(p,     v[0], v[1], v[2], v[3]);
        red_add4(p + 4, v[4], v[5], v[6], v[7]);
        red_add1(p + 8, v[8]);
    }
}

// inline BN param computation: threads c<C write sP[c]=scale, sP[C+c]=shift.
// Caller must __syncthreads() afterwards.
__device__ __forceinline__ void compute_bn(const double* st, int C, double inv,
                                           const float* gamma, const float* beta,
                                           float* sP) {
    int c = threadIdx.x;
    if (c < C) {
        double mean = st[c] * inv;
        double var  = st[18 + c] * inv - mean * mean;
        float sc = __ldg(gamma + c) * rsqrtf((float)var + 1e-5f);
        sP[c] = sc;
        sP[C + c] = __ldg(beta + c) - (float)mean * sc;
    }
}

// flush register stats (C channels of s,q) to global double slot via smem
__device__ __forceinline__ void stats_flush(float* s, float* q, int C,
                                            double* st, float* racc) {
    int lane = threadIdx.x & 31;
    #pragma unroll
    for (int c = 0; c < 18; c++) {
        if (c >= C) break;
        float ss = warp_sum(s[c]);
        float qq = warp_sum(q[c]);
        if (lane == 0) { atomicAdd(&racc[c], ss); atomicAdd(&racc[18 + c], qq); }
    }
    __syncthreads();
    int t = threadIdx.x;
    if (t < C) atomicAdd(&st[t], (double)racc[t]);
    if (t >= 18 && t < 18 + C) atomicAdd(&st[t], (double)racc[t]);
}

// ---------------- kernels ----------------
__global__ void __launch_bounds__(256) k_init() {
    int i = blockIdx.x * 256 + threadIdx.x;
    if (i < GG * PS) { g_vn[i] = 0.f; g_gs[i] = 0.f; }
    if (i < 108) { g_stZ1[i] = 0.0; g_stZ2[i] = 0.0; }
    if (i < 72)  { g_stV1[i] = 0.0; g_stV2[i] = 0.0; }
    if (i < 9)   g_outacc[i] = 0.0;
}

// AtomEncoder: h_in = sum_f atom_emb[f, x[n,f]]; zero msg buffer; graph sums of h_in
__global__ void __launch_bounds__(256) k_atom(const float* __restrict__ atom_emb,
                                              const int* __restrict__ x,
                                              const int* __restrict__ batch) {
    int base = blockIdx.x * (256 * NITER) + threadIdx.x;
    #pragma unroll
    for (int i = 0; i < NITER; i++) {
        int n = base + i * 256;
        float h[9];
        #pragma unroll
        for (int k = 0; k < 9; k++) h[k] = 0.f;
        #pragma unroll
        for (int f = 0; f < 9; f++) {
            int v = __ldg(x + (size_t)n * 9 + f);
            const float* row = atom_emb + ((size_t)f * 119 + v) * 9;
            #pragma unroll
            for (int k = 0; k < 9; k++) h[k] += __ldg(row + k);
        }
        float4* hp = (float4*)(g_hin + (size_t)n * PS);
        hp[0] = make_float4(h[0], h[1], h[2], h[3]);
        hp[1] = make_float4(h[4], h[5], h[6], h[7]);
        hp[2] = make_float4(h[8], 0.f, 0.f, 0.f);
        float4 zz = make_float4(0.f, 0.f, 0.f, 0.f);
        float4* bp = (float4*)(g_buf + (size_t)n * PS);
        bp[0] = zz; bp[1] = zz; bp[2] = zz;
        int g = __ldg(batch + n);
        seg_atomic9(g, h, g_gs);
    }
}

// GIN message: relu(h_in[src] + bond_emb sum) scatter-added at dst; 2 edges/thread
__global__ void __launch_bounds__(256) k_edge(const float* __restrict__ bond,
                                              const int* __restrict__ src,
                                              const int* __restrict__ dst,
                                              const int* __restrict__ ea) {
    __shared__ float B[162];
    if (threadIdx.x < 162) B[threadIdx.x] = bond[threadIdx.x];
    __syncthreads();
    int e0 = blockIdx.x * 512 + threadIdx.x;
    int e1 = e0 + 256;
    int s0 = __ldg(src + e0), s1 = __ldg(src + e1);
    int d0 = __ldg(dst + e0), d1 = __ldg(dst + e1);
    const float4* hp0 = (const float4*)(g_hin + (size_t)s0 * PS);
    const float4* hp1 = (const float4*)(g_hin + (size_t)s1 * PS);
    float4 A0 = hp0[0], A1 = hp0[1], A2 = hp0[2];
    float4 C0 = hp1[0], C1 = hp1[1], C2 = hp1[2];
    int a00 = __ldg(ea + (size_t)3 * e0),     a01 = __ldg(ea + (size_t)3 * e0 + 1),
        a02 = __ldg(ea + (size_t)3 * e0 + 2);
    int a10 = __ldg(ea + (size_t)3 * e1),     a11 = __ldg(ea + (size_t)3 * e1 + 1),
        a12 = __ldg(ea + (size_t)3 * e1 + 2);
    const float* b00 = B + a00 * 9;       const float* b01 = B + 54 + a01 * 9;
    const float* b02 = B + 108 + a02 * 9;
    const float* b10 = B + a10 * 9;       const float* b11 = B + 54 + a11 * 9;
    const float* b12 = B + 108 + a12 * 9;
    float hv0[9] = {A0.x, A0.y, A0.z, A0.w, A1.x, A1.y, A1.z, A1.w, A2.x};
    float hv1[9] = {C0.x, C0.y, C0.z, C0.w, C1.x, C1.y, C1.z, C1.w, C2.x};
    float m0[9], m1[9];
    #pragma unroll
    for (int k = 0; k < 9; k++) {
        m0[k] = fmaxf(hv0[k] + b00[k] + b01[k] + b02[k], 0.f);
        m1[k] = fmaxf(hv1[k] + b10[k] + b11[k] + b12[k], 0.f);
    }
    float* p0 = g_buf + (size_t)d0 * PS;
    float* p1 = g_buf + (size_t)d1 * PS;
    red_add4(p0,     m0[0], m0[1], m0[2], m0[3]);
    red_add4(p0 + 4, m0[4], m0[5], m0[6], m0[7]);
    red_add1(p0 + 8, m0[8]);
    red_add4(p1,     m1[0], m1[1], m1[2], m1[3]);
    red_add4(p1 + 4, m1[4], m1[5], m1[6], m1[7]);
    red_add1(p1 + 8, m1[8]);
}

// z = (1+eps)*h_in + aggr ; write z ; register-accumulated stats of z@W1+b1 (18 ch)
__global__ void __launch_bounds__(256) k_nodeZ(const float* __restrict__ W1,
                                               const float* __restrict__ b1,
                                               const float* __restrict__ eps_ptr, int l) {
    __shared__ float sW[162], sb[18], racc[36];
    int t = threadIdx.x;
    if (t < 162) sW[t] = W1[t];
    if (t < 18)  sb[t] = b1[t];
    if (t < 36)  racc[t] = 0.f;
    __syncthreads();
    float eps1 = 1.f + __ldg(eps_ptr);
    float s[18], q[18];
    #pragma unroll
    for (int c = 0; c < 18; c++) { s[c] = 0.f; q[c] = 0.f; }
    int base = blockIdx.x * (256 * NITER) + t;
    #pragma unroll
    for (int i = 0; i < NITER; i++) {
        int n = base + i * 256;
        float4* bp = (float4*)(g_buf + (size_t)n * PS);
        const float4* hp = (const float4*)(g_hin + (size_t)n * PS);
        float4 a = bp[0], b4 = bp[1], c4 = bp[2];
        float4 ha = hp[0], hb = hp[1], hc = hp[2];
        float z[9];
        z[0] = fmaf(eps1, ha.x, a.x);  z[1] = fmaf(eps1, ha.y, a.y);
        z[2] = fmaf(eps1, ha.z, a.z);  z[3] = fmaf(eps1, ha.w, a.w);
        z[4] = fmaf(eps1, hb.x, b4.x); z[5] = fmaf(eps1, hb.y, b4.y);
        z[6] = fmaf(eps1, hb.z, b4.z); z[7] = fmaf(eps1, hb.w, b4.w);
        z[8] = fmaf(eps1, hc.x, c4.x);
        bp[0] = make_float4(z[0], z[1], z[2], z[3]);
        bp[1] = make_float4(z[4], z[5], z[6], z[7]);
        bp[2] = make_float4(z[8], 0.f, 0.f, 0.f);
        #pragma unroll
        for (int c = 0; c < 18; c++) {
            float z1 = sb[c];
            #pragma unroll
            for (int j = 0; j < 9; j++) z1 = fmaf(z[j], sW[j * 18 + c], z1);
            s[c] += z1;
            q[c] = fmaf(z1, z1, q[c]);
        }
    }
    stats_flush(s, q, 18, g_stZ1 + l * 36, racc);
}

// y = relu(BN1(z@W1+b1)) (params inline); z2 = y@W2+b2; write z2; stats of z2 (9 ch)
__global__ void __launch_bounds__(256) k_nodeY(const float* __restrict__ W1,
                                               const float* __restrict__ b1,
                                               const float* __restrict__ W2,
                                               const float* __restrict__ b2,
                                               const float* __restrict__ bn1_g,
                                               const float* __restrict__ bn1_b, int l) {
    __shared__ float sW1[162], sW2[162], sb1[18], sb2[9], sP[36], racc[36];
    int t = threadIdx.x;
    if (t < 162) { sW1[t] = W1[t]; sW2[t] = W2[t]; }
    if (t < 18) sb1[t] = b1[t];
    if (t < 9)  sb2[t] = b2[t];
    if (t < 36) racc[t] = 0.f;
    compute_bn(g_stZ1 + l * 36, 18, 1.0 / (double)NN, bn1_g, bn1_b, sP);
    __syncthreads();
    float s[9], q[9];
    #pragma unroll
    for (int c = 0; c < 9; c++) { s[c] = 0.f; q[c] = 0.f; }
    int base = blockIdx.x * (256 * NITER) + t;
    #pragma unroll
    for (int i = 0; i < NITER; i++) {
        int n = base + i * 256;
        float4* bp = (float4*)(g_buf + (size_t)n * PS);
        float4 a = bp[0], b4 = bp[1], c4 = bp[2];
        float z[9] = {a.x, a.y, a.z, a.w, b4.x, b4.y, b4.z, b4.w, c4.x};
        float z2[9];
        #pragma unroll
        for (int c = 0; c < 9; c++) z2[c] = sb2[c];
        #pragma unroll
        for (int c = 0; c < 18; c++) {
            float z1 = sb1[c];
            #pragma unroll
            for (int j = 0; j < 9; j++) z1 = fmaf(z[j], sW1[j * 18 + c], z1);
            float y = fmaxf(fmaf(z1, sP[c], sP[18 + c]), 0.f);
            #pragma unroll
            for (int j = 0; j < 9; j++) z2[j] = fmaf(y, sW2[c * 9 + j], z2[j]);
        }
        bp[0] = make_float4(z2[0], z2[1], z2[2], z2[3]);
        bp[1] = make_float4(z2[4], z2[5], z2[6], z2[7]);
        bp[2] = make_float4(z2[8], 0.f, 0.f, 0.f);
        #pragma unroll
        for (int c = 0; c < 9; c++) {
            s[c] += z2[c];
            q[c] = fmaf(z2[c], z2[c], q[c]);
        }
    }
    stats_flush(s, q, 9, g_stZ2 + l * 36, racc);
}

// VN step A: vn_tmp = graphsum + vn (stored back into g_gs); stats of vn_tmp@vnW1+vnb1
__global__ void __launch_bounds__(256) k_vnA(const float* __restrict__ W1,
                                             const float* __restrict__ b1, int l) {
    __shared__ float sW[162], sb[18], racc[36];
    int t = threadIdx.x;
    if (t < 162) sW[t] = W1[t];
    if (t < 18)  sb[t] = b1[t];
    if (t < 36)  racc[t] = 0.f;
    __syncthreads();
    int g = blockIdx.x * 256 + t;
    float4* gp = (float4*)(g_gs + (size_t)g * PS);
    const float4* vp = (const float4*)(g_vn + (size_t)g * PS);
    float4 a = gp[0], b4 = gp[1], c4 = gp[2];
    float4 va = vp[0], vb = vp[1], vc = vp[2];
    float vt[9] = {a.x + va.x, a.y + va.y, a.z + va.z, a.w + va.w,
                   b4.x + vb.x, b4.y + vb.y, b4.z + vb.z, b4.w + vb.w, c4.x + vc.x};
    gp[0] = make_float4(vt[0], vt[1], vt[2], vt[3]);
    gp[1] = make_float4(vt[4], vt[5], vt[6], vt[7]);
    gp[2] = make_float4(vt[8], 0.f, 0.f, 0.f);
    float s[18], q[18];
    #pragma unroll
    for (int c = 0; c < 18; c++) {
        float u = sb[c];
        #pragma unroll
        for (int j = 0; j < 9; j++) u = fmaf(vt[j], sW[j * 18 + c], u);
        s[c] = u; q[c] = u * u;
    }
    stats_flush(s, q, 18, g_stV1 + l * 36, racc);
}

// VN step B: t = relu(BN1(u1)) (inline params); u2 = t@vnW2+vnb2 -> g_gs; stats of u2
__global__ void __launch_bounds__(256) k_vnB(const float* __restrict__ W1,
                                             const float* __restrict__ b1,
                                             const float* __restrict__ W2,
                                             const float* __restrict__ b2,
                                             const float* __restrict__ bn_g,
                                             const float* __restrict__ bn_b, int l) {
    __shared__ float sW1[162], sW2[162], sb1[18], sb2[9], sP[36], racc[36];
    int t = threadIdx.x;
    if (t < 162) { sW1[t] = W1[t]; sW2[t] = W2[t]; }
    if (t < 18) sb1[t] = b1[t];
    if (t < 9)  sb2[t] = b2[t];
    if (t < 36) racc[t] = 0.f;
    compute_bn(g_stV1 + l * 36, 18, 1.0 / (double)GG, bn_g, bn_b, sP);
    __syncthreads();
    int g = blockIdx.x * 256 + t;
    float4* gp = (float4*)(g_gs + (size_t)g * PS);
    float4 a = gp[0], b4 = gp[1], c4 = gp[2];
    float vt[9] = {a.x, a.y, a.z, a.w, b4.x, b4.y, b4.z, b4.w, c4.x};
    float u2[9];
    #pragma unroll
    for (int c = 0; c < 9; c++) u2[c] = sb2[c];
    #pragma unroll
    for (int c = 0; c < 18; c++) {
        float u = sb1[c];
        #pragma unroll
        for (int j = 0; j < 9; j++) u = fmaf(vt[j], sW1[j * 18 + c], u);
        float y = fmaxf(fmaf(u, sP[c], sP[18 + c]), 0.f);
        #pragma unroll
        for (int j = 0; j < 9; j++) u2[j] = fmaf(y, sW2[c * 9 + j], u2[j]);
    }
    gp[0] = make_float4(u2[0], u2[1], u2[2], u2[3]);
    gp[1] = make_float4(u2[4], u2[5], u2[6], u2[7]);
    gp[2] = make_float4(u2[8], 0.f, 0.f, 0.f);
    float s[9], q[9];
    #pragma unroll
    for (int c = 0; c < 9; c++) { s[c] = u2[c]; q[c] = u2[c] * u2[c]; }
    stats_flush(s, q, 9, g_stV2 + l * 36, racc);
}

// VN step C: vn += relu(BN2(u2)) (inline params); zero graph-sum buffer for next layer
__global__ void __launch_bounds__(256) k_vnC(const float* __restrict__ bn_g,
                                             const float* __restrict__ bn_b, int l) {
    __shared__ float sP[18];
    compute_bn(g_stV2 + l * 36, 9, 1.0 / (double)GG, bn_g, bn_b, sP);
    __syncthreads();
    int g = blockIdx.x * 256 + threadIdx.x;
    float4* gp = (float4*)(g_gs + (size_t)g * PS);
    float4* vp = (float4*)(g_vn + (size_t)g * PS);
    float4 a = gp[0], b4 = gp[1], c4 = gp[2];
    float u2[9] = {a.x, a.y, a.z, a.w, b4.x, b4.y, b4.z, b4.w, c4.x};
    float4 va = vp[0], vb = vp[1], vc = vp[2];
    float vo[9] = {va.x, va.y, va.z, va.w, vb.x, vb.y, vb.z, vb.w, vc.x};
    #pragma unroll
    for (int k = 0; k < 9; k++)
        vo[k] += fmaxf(fmaf(u2[k], sP[k], sP[9 + k]), 0.f);
    vp[0] = make_float4(vo[0], vo[1], vo[2], vo[3]);
    vp[1] = make_float4(vo[4], vo[5], vo[6], vo[7]);
    vp[2] = make_float4(vo[8], 0.f, 0.f, 0.f);
    float4 zz = make_float4(0.f, 0.f, 0.f, 0.f);
    gp[0] = zz; gp[1] = zz; gp[2] = zz;
}

// layer finish (l<2): h_new = relu(BNout(z2)) + h_in (inline params); h_in' = h_new + vn'[batch]
__global__ void __launch_bounds__(256) k_final_mid(const int* __restrict__ batch,
                                                   const float* __restrict__ bn_g,
                                                   const float* __restrict__ bn_b,
                                                   int l, int accumGS) {
    __shared__ float sP[18];
    compute_bn(g_stZ2 + l * 36, 9, 1.0 / (double)NN, bn_g, bn_b, sP);
    __syncthreads();
    int base = blockIdx.x * (256 * NITER) + threadIdx.x;
    #pragma unroll
    for (int i = 0; i < NITER; i++) {
        int n = base + i * 256;
        float4* bp = (float4*)(g_buf + (size_t)n * PS);
        float4* hp = (float4*)(g_hin + (size_t)n * PS);
        float4 a = bp[0], b4 = bp[1], c4 = bp[2];
        float z2[9] = {a.x, a.y, a.z, a.w, b4.x, b4.y, b4.z, b4.w, c4.x};
        float4 ha = hp[0], hb = hp[1], hc = hp[2];
        float hi[9] = {ha.x, ha.y, ha.z, ha.w, hb.x, hb.y, hb.z, hb.w, hc.x};
        int g = __ldg(batch + n);
        const float4* vp = (const float4*)(g_vn + (size_t)g * PS);
        float4 va = vp[0], vb = vp[1], vc = vp[2];
        float vn9[9] = {va.x, va.y, va.z, va.w, vb.x, vb.y, vb.z, vb.w, vc.x};
        float hx[9];
        #pragma unroll
        for (int k = 0; k < 9; k++) {
            float zn = fmaxf(fmaf(z2[k], sP[k], sP[9 + k]), 0.f);
            hx[k] = zn + hi[k] + vn9[k];
        }
        hp[0] = make_float4(hx[0], hx[1], hx[2], hx[3]);
        hp[1] = make_float4(hx[4], hx[5], hx[6], hx[7]);
        hp[2] = make_float4(hx[8], 0.f, 0.f, 0.f);
        float4 zz = make_float4(0.f, 0.f, 0.f, 0.f);
        bp[0] = zz; bp[1] = zz; bp[2] = zz;
        if (accumGS) seg_atomic9(g, hx, g_gs);
    }
}

// last layer finish: h = BNout(z2) + h_in (no relu, inline params); global sum
__global__ void __launch_bounds__(256) k_final_last(const float* __restrict__ bn_g,
                                                    const float* __restrict__ bn_b, int l) {
    __shared__ float sP[18], racc[9];
    compute_bn(g_stZ2 + l * 36, 9, 1.0 / (double)NN, bn_g, bn_b, sP);
    if (threadIdx.x < 9) racc[threadIdx.x] = 0.f;
    __syncthreads();
    float hs[9];
    #pragma unroll
    for (int k = 0; k < 9; k++) hs[k] = 0.f;
    int base = blockIdx.x * (256 * NITER) + threadIdx.x;
    #pragma unroll
    for (int i = 0; i < NITER; i++) {
        int n = base + i * 256;
        const float4* bp = (const float4*)(g_buf + (size_t)n * PS);
        const float4* hp = (const float4*)(g_hin + (size_t)n * PS);
        float4 a = bp[0], b4 = bp[1], c4 = bp[2];
        float z2[9] = {a.x, a.y, a.z, a.w, b4.x, b4.y, b4.z, b4.w, c4.x};
        float4 ha = hp[0], hb = hp[1], hc = hp[2];
        float hi[9] = {ha.x, ha.y, ha.z, ha.w, hb.x, hb.y, hb.z, hb.w, hc.x};
        #pragma unroll
        for (int k = 0; k < 9; k++)
            hs[k] += fmaf(z2[k], sP[k], sP[9 + k]) + hi[k];
    }
    int lane = threadIdx.x & 31;
    #pragma unroll
    for (int k = 0; k < 9; k++) {
        float v = warp_sum(hs[k]);
        if (lane == 0) atomicAdd(&racc[k], v);
    }
    __syncthreads();
    if (threadIdx.x < 9) atomicAdd(&g_outacc[threadIdx.x], (double)racc[threadIdx.x]);
}

__global__ void k_out(float* __restrict__ out) {
    if (threadIdx.x < 9) out[threadIdx.x] = (float)g_outacc[threadIdx.x];
}

// ---------------- host ----------------
extern "C" void kernel_launch(void* const* d_in, const int* in_sizes, int n_in,
                              void* d_out, int out_size) {
    const float* atom_emb = (const float*)d_in[0];
    const float* bond_emb = (const float*)d_in[1];
    const float* eps_gin  = (const float*)d_in[2];
    const float* W1       = (const float*)d_in[3];
    const float* b1       = (const float*)d_in[4];
    const float* bn1_g    = (const float*)d_in[5];
    const float* bn1_b    = (const float*)d_in[6];
    const float* W2       = (const float*)d_in[7];
    const float* b2       = (const float*)d_in[8];
    const float* bno_g    = (const float*)d_in[9];
    const float* bno_b    = (const float*)d_in[10];
    const float* vnW1     = (const float*)d_in[11];
    const float* vnb1     = (const float*)d_in[12];
    const float* vnbn1_g  = (const float*)d_in[13];
    const float* vnbn1_b  = (const float*)d_in[14];
    const float* vnW2     = (const float*)d_in[15];
    const float* vnb2     = (const float*)d_in[16];
    const float* vnbn2_g  = (const float*)d_in[17];
    const float* vnbn2_b  = (const float*)d_in[18];
    const int*   x        = (const int*)d_in[19];
    const int*   eidx     = (const int*)d_in[20];
    const int*   eattr    = (const int*)d_in[21];
    const int*   batch    = (const int*)d_in[22];
    (void)in_sizes; (void)n_in; (void)out_size;

    k_init<<<(GG * PS + 255) / 256, 256>>>();
    k_atom<<<NB_NODE, 256>>>(atom_emb, x, batch);

    for (int l = 0; l < 3; l++) {
        k_edge<<<NB_EDGE, 256>>>(bond_emb + l * 162, eidx, eidx + EE, eattr);
        k_nodeZ<<<NB_NODE, 256>>>(W1 + l * 162, b1 + l * 18, eps_gin + l, l);
        k_nodeY<<<NB_NODE, 256>>>(W1 + l * 162, b1 + l * 18, W2 + l * 162, b2 + l * 9,
                                  bn1_g + l * 18, bn1_b + l * 18, l);
        if (l < 2) {
            k_vnA<<<NB_G, 256>>>(vnW1 + l * 162, vnb1 + l * 18, l);
            k_vnB<<<NB_G, 256>>>(vnW1 + l * 162, vnb1 + l * 18, vnW2 + l * 162,
                                 vnb2 + l * 9, vnbn1_g + l * 18, vnbn1_b + l * 18, l);
            k_vnC<<<NB_G, 256>>>(vnbn2_g + l * 9, vnbn2_b + l * 9, l);
            k_final_mid<<<NB_NODE, 256>>>(batch, bno_g + l * 9, bno_b + l * 9, l,
                                          (l == 0) ? 1 : 0);
        } else {
            k_final_last<<<NB_NODE, 256>>>(bno_g + l * 9, bno_b + l * 9, l);
        }
    }
    k_out<<<1, 32>>>((float*)d_out);
}

// round 7
// speedup vs baseline: 1.0459x; 1.0459x over previous
#include <cuda_runtime.h>

#define NN 1048576
#define EE 8388608
#define GG 32768
#define PS 12   // padded row stride (9 ch + 3 pad) -> 48B, 16B-aligned
#define NITER 4
#define NB_NODE (NN / (256 * NITER))   // 1024
#define NB_EDGE (EE / 256)             // 32768
#define NB_G (GG / 256)                // 128

// ---------------- device state (no allocation allowed) ----------------
__device__ __align__(16) float  g_hin[(size_t)NN * PS];
__device__ __align__(16) float  g_buf[(size_t)NN * PS];
__device__ __align__(16) float  g_vn [(size_t)GG * PS];
__device__ __align__(16) float  g_gs [(size_t)GG * PS];
// per-layer raw BN stats: sum at [c], sumsq at [18+c], 36-stride per layer
__device__ double g_stZ1[3 * 36];   // z@W1+b1, 18 ch
__device__ double g_stZ2[3 * 36];   // z2, 9 ch
__device__ double g_stV1[2 * 36];   // vn MLP hidden, 18 ch
__device__ double g_stV2[2 * 36];   // vn MLP out, 9 ch
__device__ double g_outacc[9];

// ---------------- helpers ----------------
__device__ __forceinline__ void red_add4(float* p, float a, float b, float c, float d) {
    asm volatile("red.global.add.v4.f32 [%0], {%1,%2,%3,%4};"
                 :: "l"(__cvta_generic_to_global(p)), "f"(a), "f"(b), "f"(c), "f"(d) : "memory");
}
__device__ __forceinline__ void red_add1(float* p, float a) {
    asm volatile("red.global.add.f32 [%0], %1;"
                 :: "l"(__cvta_generic_to_global(p)), "f"(a) : "memory");
}
__device__ __forceinline__ float warp_sum(float v) {
    #pragma unroll
    for (int off = 16; off > 0; off >>= 1) v += __shfl_down_sync(0xffffffffu, v, off);
    return v;
}

// warp-level segmented sum over sorted keys, then 3 vector atomics per segment head
__device__ __forceinline__ void seg_atomic9(int key, float v[9], float* dstBase) {
    int lane = threadIdx.x & 31;
    #pragma unroll
    for (int off = 1; off < 32; off <<= 1) {
        int nk = __shfl_down_sync(0xffffffffu, key, off);
        float t[9];
        #pragma unroll
        for (int k = 0; k < 9; k++) t[k] = __shfl_down_sync(0xffffffffu, v[k], off);
        if (lane + off < 32 && nk == key) {
            #pragma unroll
            for (int k = 0; k < 9; k++) v[k] += t[k];
        }
    }
    int pk = __shfl_up_sync(0xffffffffu, key, 1);
    if (lane == 0 || pk != key) {
        float* p = dstBase + (size_t)key * PS;
        red_add4(p,     v[0], v[1], v[2], v[3]);
        red_add4(p + 4, v[4], v[5], v[6], v[7]);
        red_add1(p + 8, v[8]);
    }
}

// inline BN param computation: threads c<C write sP[c]=scale, sP[C+c]=shift.
// Caller must __syncthreads() afterwards.
__device__ __forceinline__ void compute_bn(const double* st, int C, double inv,
                                           const float* gamma, const float* beta,
                                           float* sP) {
    int c = threadIdx.x;
    if (c < C) {
        double mean = st[c] * inv;
        double var  = st[18 + c] * inv - mean * mean;
        float sc = __ldg(gamma + c) * rsqrtf((float)var + 1e-5f);
        sP[c] = sc;
        sP[C + c] = __ldg(beta + c) - (float)mean * sc;
    }
}

// flush register stats (C channels of s,q) to global double slot via smem
__device__ __forceinline__ void stats_flush(const float* s, const float* q, int C,
                                            double* st, float* racc) {
    int lane = threadIdx.x & 31;
    for (int c = 0; c < C; c++) {
        float ss = warp_sum(s[c]);
        float qq = warp_sum(q[c]);
        if (lane == 0) { atomicAdd(&racc[c], ss); atomicAdd(&racc[18 + c], qq); }
    }
    __syncthreads();
    int t = threadIdx.x;
    if (t < C) atomicAdd(&st[t], (double)racc[t]);
    if (t >= 18 && t < 18 + C) atomicAdd(&st[t], (double)racc[t]);
}

// ---------------- kernels ----------------
__global__ void __launch_bounds__(256) k_init() {
    int i = blockIdx.x * 256 + threadIdx.x;
    if (i < GG * PS) { g_vn[i] = 0.f; g_gs[i] = 0.f; }
    if (i < 108) { g_stZ1[i] = 0.0; g_stZ2[i] = 0.0; }
    if (i < 72)  { g_stV1[i] = 0.0; g_stV2[i] = 0.0; }
    if (i < 9)   g_outacc[i] = 0.0;
}

// AtomEncoder: h_in = sum_f atom_emb[f, x[n,f]]; zero msg buffer; graph sums of h_in
__global__ void __launch_bounds__(256, 4) k_atom(const float* __restrict__ atom_emb,
                                                 const int* __restrict__ x,
                                                 const int* __restrict__ batch) {
    int base = blockIdx.x * (256 * NITER) + threadIdx.x;
    #pragma unroll 1
    for (int i = 0; i < NITER; i++) {
        int n = base + i * 256;
        float h[9];
        #pragma unroll
        for (int k = 0; k < 9; k++) h[k] = 0.f;
        #pragma unroll
        for (int f = 0; f < 9; f++) {
            int v = __ldg(x + (size_t)n * 9 + f);
            const float* row = atom_emb + ((size_t)f * 119 + v) * 9;
            #pragma unroll
            for (int k = 0; k < 9; k++) h[k] += __ldg(row + k);
        }
        float4* hp = (float4*)(g_hin + (size_t)n * PS);
        hp[0] = make_float4(h[0], h[1], h[2], h[3]);
        hp[1] = make_float4(h[4], h[5], h[6], h[7]);
        hp[2] = make_float4(h[8], 0.f, 0.f, 0.f);
        float4 zz = make_float4(0.f, 0.f, 0.f, 0.f);
        float4* bp = (float4*)(g_buf + (size_t)n * PS);
        bp[0] = zz; bp[1] = zz; bp[2] = zz;
        int g = __ldg(batch + n);
        seg_atomic9(g, h, g_gs);
    }
}

// GIN message: relu(h_in[src] + bond_emb sum) scatter-added at dst
__global__ void __launch_bounds__(256) k_edge(const float* __restrict__ bond,
                                              const int* __restrict__ src,
                                              const int* __restrict__ dst,
                                              const int* __restrict__ ea) {
    __shared__ float B[162];
    if (threadIdx.x < 162) B[threadIdx.x] = bond[threadIdx.x];
    __syncthreads();
    int e = blockIdx.x * 256 + threadIdx.x;   // grid exactly covers EE
    int s  = __ldg(src + e);
    int d  = __ldg(dst + e);
    int a0 = __ldg(ea + (size_t)3 * e);
    int a1 = __ldg(ea + (size_t)3 * e + 1);
    int a2 = __ldg(ea + (size_t)3 * e + 2);
    const float* b0 = B + a0 * 9;
    const float* b1 = B + 54 + a1 * 9;
    const float* b2 = B + 108 + a2 * 9;
    const float4* hp = (const float4*)(g_hin + (size_t)s * PS);
    float4 h0 = hp[0], h1 = hp[1], h2 = hp[2];
    float hv[9] = {h0.x, h0.y, h0.z, h0.w, h1.x, h1.y, h1.z, h1.w, h2.x};
    float m[9];
    #pragma unroll
    for (int k = 0; k < 9; k++) m[k] = fmaxf(hv[k] + b0[k] + b1[k] + b2[k], 0.f);
    float* p = g_buf + (size_t)d * PS;
    red_add4(p,     m[0], m[1], m[2], m[3]);
    red_add4(p + 4, m[4], m[5], m[6], m[7]);
    red_add1(p + 8, m[8]);
}

// z = (1+eps)*h_in + aggr ; write z ; register-accumulated stats of z@W1+b1 (18 ch)
__global__ void __launch_bounds__(256, 4) k_nodeZ(const float* __restrict__ W1,
                                                  const float* __restrict__ b1,
                                                  const float* __restrict__ eps_ptr, int l) {
    __shared__ float sW[162], sb[18], racc[36];
    int t = threadIdx.x;
    if (t < 162) sW[t] = W1[t];
    if (t < 18)  sb[t] = b1[t];
    if (t < 36)  racc[t] = 0.f;
    __syncthreads();
    float eps1 = 1.f + __ldg(eps_ptr);
    float s[18], q[18];
    #pragma unroll
    for (int c = 0; c < 18; c++) { s[c] = 0.f; q[c] = 0.f; }
    int base = blockIdx.x * (256 * NITER) + t;
    #pragma unroll 1
    for (int i = 0; i < NITER; i++) {
        int n = base + i * 256;
        float4* bp = (float4*)(g_buf + (size_t)n * PS);
        const float4* hp = (const float4*)(g_hin + (size_t)n * PS);
        float4 a = bp[0], b4 = bp[1], c4 = bp[2];
        float4 ha = hp[0], hb = hp[1], hc = hp[2];
        float z[9];
        z[0] = fmaf(eps1, ha.x, a.x);  z[1] = fmaf(eps1, ha.y, a.y);
        z[2] = fmaf(eps1, ha.z, a.z);  z[3] = fmaf(eps1, ha.w, a.w);
        z[4] = fmaf(eps1, hb.x, b4.x); z[5] = fmaf(eps1, hb.y, b4.y);
        z[6] = fmaf(eps1, hb.z, b4.z); z[7] = fmaf(eps1, hb.w, b4.w);
        z[8] = fmaf(eps1, hc.x, c4.x);
        bp[0] = make_float4(z[0], z[1], z[2], z[3]);
        bp[1] = make_float4(z[4], z[5], z[6], z[7]);
        bp[2] = make_float4(z[8], 0.f, 0.f, 0.f);
        #pragma unroll
        for (int c = 0; c < 18; c++) {
            float z1 = sb[c];
            #pragma unroll
            for (int j = 0; j < 9; j++) z1 = fmaf(z[j], sW[j * 18 + c], z1);
            s[c] += z1;
            q[c] = fmaf(z1, z1, q[c]);
        }
    }
    stats_flush(s, q, 18, g_stZ1 + l * 36, racc);
}

// y = relu(BN1(z@W1+b1)) (params inline); z2 = y@W2+b2; write z2; stats of z2 (9 ch)
__global__ void __launch_bounds__(256, 3) k_nodeY(const float* __restrict__ W1,
                                                  const float* __restrict__ b1,
                                                  const float* __restrict__ W2,
                                                  const float* __restrict__ b2,
                                                  const float* __restrict__ bn1_g,
                                                  const float* __restrict__ bn1_b, int l) {
    __shared__ float sW1[162], sW2[162], sb1[18], sb2[9], sP[36], racc[36];
    int t = threadIdx.x;
    if (t < 162) { sW1[t] = W1[t]; sW2[t] = W2[t]; }
    if (t < 18) sb1[t] = b1[t];
    if (t < 9)  sb2[t] = b2[t];
    if (t < 36) racc[t] = 0.f;
    compute_bn(g_stZ1 + l * 36, 18, 1.0 / (double)NN, bn1_g, bn1_b, sP);
    __syncthreads();
    float s[9], q[9];
    #pragma unroll
    for (int c = 0; c < 9; c++) { s[c] = 0.f; q[c] = 0.f; }
    int base = blockIdx.x * (256 * NITER) + t;
    #pragma unroll 1
    for (int i = 0; i < NITER; i++) {
        int n = base + i * 256;
        float4* bp = (float4*)(g_buf + (size_t)n * PS);
        float4 a = bp[0], b4 = bp[1], c4 = bp[2];
        float z[9] = {a.x, a.y, a.z, a.w, b4.x, b4.y, b4.z, b4.w, c4.x};
        float z2[9];
        #pragma unroll
        for (int c = 0; c < 9; c++) z2[c] = sb2[c];
        #pragma unroll
        for (int c = 0; c < 18; c++) {
            float z1 = sb1[c];
            #pragma unroll
            for (int j = 0; j < 9; j++) z1 = fmaf(z[j], sW1[j * 18 + c], z1);
            float y = fmaxf(fmaf(z1, sP[c], sP[18 + c]), 0.f);
            #pragma unroll
            for (int j = 0; j < 9; j++) z2[j] = fmaf(y, sW2[c * 9 + j], z2[j]);
        }
        bp[0] = make_float4(z2[0], z2[1], z2[2], z2[3]);
        bp[1] = make_float4(z2[4], z2[5], z2[6], z2[7]);
        bp[2] = make_float4(z2[8], 0.f, 0.f, 0.f);
        #pragma unroll
        for (int c = 0; c < 9; c++) {
            s[c] += z2[c];
            q[c] = fmaf(z2[c], z2[c], q[c]);
        }
    }
    stats_flush(s, q, 9, g_stZ2 + l * 36, racc);
}

// VN step A: vn_tmp = graphsum + vn (stored back into g_gs); stats of vn_tmp@vnW1+vnb1
__global__ void __launch_bounds__(256) k_vnA(const float* __restrict__ W1,
                                             const float* __restrict__ b1, int l) {
    __shared__ float sW[162], sb[18], racc[36];
    int t = threadIdx.x;
    if (t < 162) sW[t] = W1[t];
    if (t < 18)  sb[t] = b1[t];
    if (t < 36)  racc[t] = 0.f;
    __syncthreads();
    int g = blockIdx.x * 256 + t;
    float4* gp = (float4*)(g_gs + (size_t)g * PS);
    const float4* vp = (const float4*)(g_vn + (size_t)g * PS);
    float4 a = gp[0], b4 = gp[1], c4 = gp[2];
    float4 va = vp[0], vb = vp[1], vc = vp[2];
    float vt[9] = {a.x + va.x, a.y + va.y, a.z + va.z, a.w + va.w,
                   b4.x + vb.x, b4.y + vb.y, b4.z + vb.z, b4.w + vb.w, c4.x + vc.x};
    gp[0] = make_float4(vt[0], vt[1], vt[2], vt[3]);
    gp[1] = make_float4(vt[4], vt[5], vt[6], vt[7]);
    gp[2] = make_float4(vt[8], 0.f, 0.f, 0.f);
    float s[18], q[18];
    #pragma unroll
    for (int c = 0; c < 18; c++) {
        float u = sb[c];
        #pragma unroll
        for (int j = 0; j < 9; j++) u = fmaf(vt[j], sW[j * 18 + c], u);
        s[c] = u; q[c] = u * u;
    }
    stats_flush(s, q, 18, g_stV1 + l * 36, racc);
}

// VN step B: t = relu(BN1(u1)) (inline params); u2 = t@vnW2+vnb2 -> g_gs; stats of u2
__global__ void __launch_bounds__(256) k_vnB(const float* __restrict__ W1,
                                             const float* __restrict__ b1,
                                             const float* __restrict__ W2,
                                             const float* __restrict__ b2,
                                             const float* __restrict__ bn_g,
                                             const float* __restrict__ bn_b, int l) {
    __shared__ float sW1[162], sW2[162], sb1[18], sb2[9], sP[36], racc[36];
    int t = threadIdx.x;
    if (t < 162) { sW1[t] = W1[t]; sW2[t] = W2[t]; }
    if (t < 18) sb1[t] = b1[t];
    if (t < 9)  sb2[t] = b2[t];
    if (t < 36) racc[t] = 0.f;
    compute_bn(g_stV1 + l * 36, 18, 1.0 / (double)GG, bn_g, bn_b, sP);
    __syncthreads();
    int g = blockIdx.x * 256 + t;
    float4* gp = (float4*)(g_gs + (size_t)g * PS);
    float4 a = gp[0], b4 = gp[1], c4 = gp[2];
    float vt[9] = {a.x, a.y, a.z, a.w, b4.x, b4.y, b4.z, b4.w, c4.x};
    float u2[9];
    #pragma unroll
    for (int c = 0; c < 9; c++) u2[c] = sb2[c];
    #pragma unroll
    for (int c = 0; c < 18; c++) {
        float u = sb1[c];
        #pragma unroll
        for (int j = 0; j < 9; j++) u = fmaf(vt[j], sW1[j * 18 + c], u);
        float y = fmaxf(fmaf(u, sP[c], sP[18 + c]), 0.f);
        #pragma unroll
        for (int j = 0; j < 9; j++) u2[j] = fmaf(y, sW2[c * 9 + j], u2[j]);
    }
    gp[0] = make_float4(u2[0], u2[1], u2[2], u2[3]);
    gp[1] = make_float4(u2[4], u2[5], u2[6], u2[7]);
    gp[2] = make_float4(u2[8], 0.f, 0.f, 0.f);
    float s[9], q[9];
    #pragma unroll
    for (int c = 0; c < 9; c++) { s[c] = u2[c]; q[c] = u2[c] * u2[c]; }
    stats_flush(s, q, 9, g_stV2 + l * 36, racc);
}

// VN step C: vn += relu(BN2(u2)) (inline params); zero graph-sum buffer for next layer
__global__ void __launch_bounds__(256) k_vnC(const float* __restrict__ bn_g,
                                             const float* __restrict__ bn_b, int l) {
    __shared__ float sP[18];
    compute_bn(g_stV2 + l * 36, 9, 1.0 / (double)GG, bn_g, bn_b, sP);
    __syncthreads();
    int g = blockIdx.x * 256 + threadIdx.x;
    float4* gp = (float4*)(g_gs + (size_t)g * PS);
    float4* vp = (float4*)(g_vn + (size_t)g * PS);
    float4 a = gp[0], b4 = gp[1], c4 = gp[2];
    float u2[9] = {a.x, a.y, a.z, a.w, b4.x, b4.y, b4.z, b4.w, c4.x};
    float4 va = vp[0], vb = vp[1], vc = vp[2];
    float vo[9] = {va.x, va.y, va.z, va.w, vb.x, vb.y, vb.z, vb.w, vc.x};
    #pragma unroll
    for (int k = 0; k < 9; k++)
        vo[k] += fmaxf(fmaf(u2[k], sP[k], sP[9 + k]), 0.f);
    vp[0] = make_float4(vo[0], vo[1], vo[2], vo[3]);
    vp[1] = make_float4(vo[4], vo[5], vo[6], vo[7]);
    vp[2] = make_float4(vo[8], 0.f, 0.f, 0.f);
    float4 zz = make_float4(0.f, 0.f, 0.f, 0.f);
    gp[0] = zz; gp[1] = zz; gp[2] = zz;
}

// layer finish (l<2): h_new = relu(BNout(z2)) + h_in (inline params); h_in' = h_new + vn'[batch]
__global__ void __launch_bounds__(256, 4) k_final_mid(const int* __restrict__ batch,
                                                      const float* __restrict__ bn_g,
                                                      const float* __restrict__ bn_b,
                                                      int l, int accumGS) {
    __shared__ float sP[18];
    compute_bn(g_stZ2 + l * 36, 9, 1.0 / (double)NN, bn_g, bn_b, sP);
    __syncthreads();
    int base = blockIdx.x * (256 * NITER) + threadIdx.x;
    #pragma unroll 1
    for (int i = 0; i < NITER; i++) {
        int n = base + i * 256;
        float4* bp = (float4*)(g_buf + (size_t)n * PS);
        float4* hp = (float4*)(g_hin + (size_t)n * PS);
        float4 a = bp[0], b4 = bp[1], c4 = bp[2];
        float z2[9] = {a.x, a.y, a.z, a.w, b4.x, b4.y, b4.z, b4.w, c4.x};
        float4 ha = hp[0], hb = hp[1], hc = hp[2];
        float hi[9] = {ha.x, ha.y, ha.z, ha.w, hb.x, hb.y, hb.z, hb.w, hc.x};
        int g = __ldg(batch + n);
        const float4* vp = (const float4*)(g_vn + (size_t)g * PS);
        float4 va = vp[0], vb = vp[1], vc = vp[2];
        float vn9[9] = {va.x, va.y, va.z, va.w, vb.x, vb.y, vb.z, vb.w, vc.x};
        float hx[9];
        #pragma unroll
        for (int k = 0; k < 9; k++) {
            float zn = fmaxf(fmaf(z2[k], sP[k], sP[9 + k]), 0.f);
            hx[k] = zn + hi[k] + vn9[k];
        }
        hp[0] = make_float4(hx[0], hx[1], hx[2], hx[3]);
        hp[1] = make_float4(hx[4], hx[5], hx[6], hx[7]);
        hp[2] = make_float4(hx[8], 0.f, 0.f, 0.f);
        float4 zz = make_float4(0.f, 0.f, 0.f, 0.f);
        bp[0] = zz; bp[1] = zz; bp[2] = zz;
        if (accumGS) seg_atomic9(g, hx, g_gs);
    }
}

// last layer finish: h = BNout(z2) + h_in (no relu, inline params); global sum
__global__ void __launch_bounds__(256, 4) k_final_last(const float* __restrict__ bn_g,
                                                       const float* __restrict__ bn_b, int l) {
    __shared__ float sP[18], racc[9];
    compute_bn(g_stZ2 + l * 36, 9, 1.0 / (double)NN, bn_g, bn_b, sP);
    if (threadIdx.x < 9) racc[threadIdx.x] = 0.f;
    __syncthreads();
    float hs[9];
    #pragma unroll
    for (int k = 0; k < 9; k++) hs[k] = 0.f;
    int base = blockIdx.x * (256 * NITER) + threadIdx.x;
    #pragma unroll 1
    for (int i = 0; i < NITER; i++) {
        int n = base + i * 256;
        const float4* bp = (const float4*)(g_buf + (size_t)n * PS);
        const float4* hp = (const float4*)(g_hin + (size_t)n * PS);
        float4 a = bp[0], b4 = bp[1], c4 = bp[2];
        float z2[9] = {a.x, a.y, a.z, a.w, b4.x, b4.y, b4.z, b4.w, c4.x};
        float4 ha = hp[0], hb = hp[1], hc = hp[2];
        float hi[9] = {ha.x, ha.y, ha.z, ha.w, hb.x, hb.y, hb.z, hb.w, hc.x};
        #pragma unroll
        for (int k = 0; k < 9; k++)
            hs[k] += fmaf(z2[k], sP[k], sP[9 + k]) + hi[k];
    }
    int lane = threadIdx.x & 31;
    #pragma unroll
    for (int k = 0; k < 9; k++) {
        float v = warp_sum(hs[k]);
        if (lane == 0) atomicAdd(&racc[k], v);
    }
    __syncthreads();
    if (threadIdx.x < 9) atomicAdd(&g_outacc[threadIdx.x], (double)racc[threadIdx.x]);
}

__global__ void k_out(float* __restrict__ out) {
    if (threadIdx.x < 9) out[threadIdx.x] = (float)g_outacc[threadIdx.x];
}

// ---------------- host ----------------
extern "C" void kernel_launch(void* const* d_in, const int* in_sizes, int n_in,
                              void* d_out, int out_size) {
    const float* atom_emb = (const float*)d_in[0];
    const float* bond_emb = (const float*)d_in[1];
    const float* eps_gin  = (const float*)d_in[2];
    const float* W1       = (const float*)d_in[3];
    const float* b1       = (const float*)d_in[4];
    const float* bn1_g    = (const float*)d_in[5];
    const float* bn1_b    = (const float*)d_in[6];
    const float* W2       = (const float*)d_in[7];
    const float* b2       = (const float*)d_in[8];
    const float* bno_g    = (const float*)d_in[9];
    const float* bno_b    = (const float*)d_in[10];
    const float* vnW1     = (const float*)d_in[11];
    const float* vnb1     = (const float*)d_in[12];
    const float* vnbn1_g  = (const float*)d_in[13];
    const float* vnbn1_b  = (const float*)d_in[14];
    const float* vnW2     = (const float*)d_in[15];
    const float* vnb2     = (const float*)d_in[16];
    const float* vnbn2_g  = (const float*)d_in[17];
    const float* vnbn2_b  = (const float*)d_in[18];
    const int*   x        = (const int*)d_in[19];
    const int*   eidx     = (const int*)d_in[20];
    const int*   eattr    = (const int*)d_in[21];
    const int*   batch    = (const int*)d_in[22];
    (void)in_sizes; (void)n_in; (void)out_size;

    k_init<<<(GG * PS + 255) / 256, 256>>>();
    k_atom<<<NB_NODE, 256>>>(atom_emb, x, batch);

    for (int l = 0; l < 3; l++) {
        k_edge<<<NB_EDGE, 256>>>(bond_emb + l * 162, eidx, eidx + EE, eattr);
        k_nodeZ<<<NB_NODE, 256>>>(W1 + l * 162, b1 + l * 18, eps_gin + l, l);
        k_nodeY<<<NB_NODE, 256>>>(W1 + l * 162, b1 + l * 18, W2 + l * 162, b2 + l * 9,
                                  bn1_g + l * 18, bn1_b + l * 18, l);
        if (l < 2) {
            k_vnA<<<NB_G, 256>>>(vnW1 + l * 162, vnb1 + l * 18, l);
            k_vnB<<<NB_G, 256>>>(vnW1 + l * 162, vnb1 + l * 18, vnW2 + l * 162,
                                 vnb2 + l * 9, vnbn1_g + l * 18, vnbn1_b + l * 18, l);
            k_vnC<<<NB_G, 256>>>(vnbn2_g + l * 9, vnbn2_b + l * 9, l);
            k_final_mid<<<NB_NODE, 256>>>(batch, bno_g + l * 9, bno_b + l * 9, l,
                                          (l == 0) ? 1 : 0);
        } else {
            k_final_last<<<NB_NODE, 256>>>(bno_g + l * 9, bno_b + l * 9, l);
        }
    }
    k_out<<<1, 32>>>((float*)d_out);
}

// round 8
// speedup vs baseline: 1.5571x; 1.4888x over previous
#include <cuda_runtime.h>

#define NN 1048576
#define EE 8388608
#define GG 32768
#define PS 12   // padded row stride (9 ch + 3 pad) -> 48B, 16B-aligned
#define NZI 8                           // nodes/thread in stats kernels
#define NB_STAT (NN / (256 * NZI))      // 512
#define NB_N (NN / 256)                 // 4096
#define NB_E (EE / 256)                 // 32768
#define NB_G (GG / 256)                 // 128

// ---------------- device state (no allocation allowed) ----------------
__device__ __align__(16) float  g_hin[(size_t)NN * PS];
__device__ __align__(16) float  g_buf[(size_t)NN * PS];
__device__ __align__(16) float  g_vn [(size_t)GG * PS];
__device__ __align__(16) float  g_gs [(size_t)GG * PS];
// per-layer raw BN stats: sum at [c], sumsq at [18+c], 36-stride per layer
__device__ double g_stZ1[3 * 36];   // z@W1+b1, 18 ch
__device__ double g_stZ2[3 * 36];   // z2, 9 ch
__device__ double g_stV1[2 * 36];   // vn MLP hidden, 18 ch
__device__ double g_stV2[2 * 36];   // vn MLP out, 9 ch
__device__ double g_outacc[9];

// ---------------- helpers ----------------
__device__ __forceinline__ void red_add4(float* p, float a, float b, float c, float d) {
    asm volatile("red.global.add.v4.f32 [%0], {%1,%2,%3,%4};"
                 :: "l"(__cvta_generic_to_global(p)), "f"(a), "f"(b), "f"(c), "f"(d) : "memory");
}
__device__ __forceinline__ void red_add1(float* p, float a) {
    asm volatile("red.global.add.f32 [%0], %1;"
                 :: "l"(__cvta_generic_to_global(p)), "f"(a) : "memory");
}
__device__ __forceinline__ float warp_sum(float v) {
    #pragma unroll
    for (int off = 16; off > 0; off >>= 1) v += __shfl_down_sync(0xffffffffu, v, off);
    return v;
}

// warp-level segmented sum over sorted keys, then 3 vector atomics per segment head
__device__ __forceinline__ void seg_atomic9(int key, float v[9], float* dstBase) {
    int lane = threadIdx.x & 31;
    #pragma unroll
    for (int off = 1; off < 32; off <<= 1) {
        int nk = __shfl_down_sync(0xffffffffu, key, off);
        float t[9];
        #pragma unroll
        for (int k = 0; k < 9; k++) t[k] = __shfl_down_sync(0xffffffffu, v[k], off);
        if (lane + off < 32 && nk == key) {
            #pragma unroll
            for (int k = 0; k < 9; k++) v[k] += t[k];
        }
    }
    int pk = __shfl_up_sync(0xffffffffu, key, 1);
    if (lane == 0 || pk != key) {
        float* p = dstBase + (size_t)key * PS;
        red_add4(p,     v[0], v[1], v[2], v[3]);
        red_add4(p + 4, v[4], v[5], v[6], v[7]);
        red_add1(p + 8, v[8]);
    }
}

// inline BN param computation: threads c<C write sP[c]=scale, sP[C+c]=shift.
// Caller must __syncthreads() afterwards.
__device__ __forceinline__ void compute_bn(const double* st, int C, double inv,
                                           const float* gamma, const float* beta,
                                           float* sP) {
    int c = threadIdx.x;
    if (c < C) {
        double mean = st[c] * inv;
        double var  = st[18 + c] * inv - mean * mean;
        float sc = __ldg(gamma + c) * rsqrtf((float)var + 1e-5f);
        sP[c] = sc;
        sP[C + c] = __ldg(beta + c) - (float)mean * sc;
    }
}

// flush register stats (C channels of s,q) to global double slot via smem
__device__ __forceinline__ void stats_flush(const float* s, const float* q, int C,
                                            double* st, float* racc) {
    int lane = threadIdx.x & 31;
    for (int c = 0; c < C; c++) {
        float ss = warp_sum(s[c]);
        float qq = warp_sum(q[c]);
        if (lane == 0) { atomicAdd(&racc[c], ss); atomicAdd(&racc[18 + c], qq); }
    }
    __syncthreads();
    int t = threadIdx.x;
    if (t < C) atomicAdd(&st[t], (double)racc[t]);
    if (t >= 18 && t < 18 + C) atomicAdd(&st[t], (double)racc[t]);
}

// ---------------- kernels ----------------
__global__ void __launch_bounds__(256) k_init() {
    int i = blockIdx.x * 256 + threadIdx.x;
    if (i < GG * PS) { g_vn[i] = 0.f; g_gs[i] = 0.f; }
    if (i < 108) { g_stZ1[i] = 0.0; g_stZ2[i] = 0.0; }
    if (i < 72)  { g_stV1[i] = 0.0; g_stV2[i] = 0.0; }
    if (i < 9)   g_outacc[i] = 0.0;
}

// AtomEncoder: h_in = sum_f atom_emb[f, x[n,f]]; zero msg buffer; graph sums of h_in
__global__ void __launch_bounds__(256) k_atom(const float* __restrict__ atom_emb,
                                              const int* __restrict__ x,
                                              const int* __restrict__ batch) {
    int n = blockIdx.x * 256 + threadIdx.x;   // grid exactly covers NN
    float h[9];
    #pragma unroll
    for (int k = 0; k < 9; k++) h[k] = 0.f;
    #pragma unroll
    for (int f = 0; f < 9; f++) {
        int v = __ldg(x + (size_t)n * 9 + f);
        const float* row = atom_emb + ((size_t)f * 119 + v) * 9;
        #pragma unroll
        for (int k = 0; k < 9; k++) h[k] += __ldg(row + k);
    }
    float4* hp = (float4*)(g_hin + (size_t)n * PS);
    hp[0] = make_float4(h[0], h[1], h[2], h[3]);
    hp[1] = make_float4(h[4], h[5], h[6], h[7]);
    hp[2] = make_float4(h[8], 0.f, 0.f, 0.f);
    float4 zz = make_float4(0.f, 0.f, 0.f, 0.f);
    float4* bp = (float4*)(g_buf + (size_t)n * PS);
    bp[0] = zz; bp[1] = zz; bp[2] = zz;
    int g = __ldg(batch + n);
    seg_atomic9(g, h, g_gs);
}

// GIN message: relu(h_in[src] + bond_emb sum) scatter-added at dst
__global__ void __launch_bounds__(256) k_edge(const float* __restrict__ bond,
                                              const int* __restrict__ src,
                                              const int* __restrict__ dst,
                                              const int* __restrict__ ea) {
    __shared__ float B[162];
    if (threadIdx.x < 162) B[threadIdx.x] = bond[threadIdx.x];
    __syncthreads();
    int e = blockIdx.x * 256 + threadIdx.x;   // grid exactly covers EE
    int s  = __ldg(src + e);
    int d  = __ldg(dst + e);
    int a0 = __ldg(ea + (size_t)3 * e);
    int a1 = __ldg(ea + (size_t)3 * e + 1);
    int a2 = __ldg(ea + (size_t)3 * e + 2);
    const float* b0 = B + a0 * 9;
    const float* b1 = B + 54 + a1 * 9;
    const float* b2 = B + 108 + a2 * 9;
    const float4* hp = (const float4*)(g_hin + (size_t)s * PS);
    float4 h0 = hp[0], h1 = hp[1], h2 = hp[2];
    float hv[9] = {h0.x, h0.y, h0.z, h0.w, h1.x, h1.y, h1.z, h1.w, h2.x};
    float m[9];
    #pragma unroll
    for (int k = 0; k < 9; k++) m[k] = fmaxf(hv[k] + b0[k] + b1[k] + b2[k], 0.f);
    float* p = g_buf + (size_t)d * PS;
    red_add4(p,     m[0], m[1], m[2], m[3]);
    red_add4(p + 4, m[4], m[5], m[6], m[7]);
    red_add1(p + 8, m[8]);
}

// z = (1+eps)*h_in + aggr ; write z ; register-accumulated stats of z@W1+b1 (18 ch)
// NZI nodes/thread, outer loop NOT unrolled (one node live), 128-reg budget (no spill)
__global__ void __launch_bounds__(256, 2) k_nodeZ(const float* __restrict__ W1,
                                                  const float* __restrict__ b1,
                                                  const float* __restrict__ eps_ptr, int l) {
    __shared__ float sW[162], sb[18], racc[36];
    int t = threadIdx.x;
    if (t < 162) sW[t] = W1[t];
    if (t < 18)  sb[t] = b1[t];
    if (t < 36)  racc[t] = 0.f;
    __syncthreads();
    float eps1 = 1.f + __ldg(eps_ptr);
    float s[18], q[18];
    #pragma unroll
    for (int c = 0; c < 18; c++) { s[c] = 0.f; q[c] = 0.f; }
    int base = blockIdx.x * (256 * NZI) + t;
    #pragma unroll 1
    for (int i = 0; i < NZI; i++) {
        int n = base + i * 256;
        float4* bp = (float4*)(g_buf + (size_t)n * PS);
        const float4* hp = (const float4*)(g_hin + (size_t)n * PS);
        float4 a = bp[0], b4 = bp[1], c4 = bp[2];
        float4 ha = hp[0], hb = hp[1], hc = hp[2];
        float z[9];
        z[0] = fmaf(eps1, ha.x, a.x);  z[1] = fmaf(eps1, ha.y, a.y);
        z[2] = fmaf(eps1, ha.z, a.z);  z[3] = fmaf(eps1, ha.w, a.w);
        z[4] = fmaf(eps1, hb.x, b4.x); z[5] = fmaf(eps1, hb.y, b4.y);
        z[6] = fmaf(eps1, hb.z, b4.z); z[7] = fmaf(eps1, hb.w, b4.w);
        z[8] = fmaf(eps1, hc.x, c4.x);
        bp[0] = make_float4(z[0], z[1], z[2], z[3]);
        bp[1] = make_float4(z[4], z[5], z[6], z[7]);
        bp[2] = make_float4(z[8], 0.f, 0.f, 0.f);
        #pragma unroll
        for (int c = 0; c < 18; c++) {
            float z1 = sb[c];
            #pragma unroll
            for (int j = 0; j < 9; j++) z1 = fmaf(z[j], sW[j * 18 + c], z1);
            s[c] += z1;
            q[c] = fmaf(z1, z1, q[c]);
        }
    }
    stats_flush(s, q, 18, g_stZ1 + l * 36, racc);
}

// y = relu(BN1(z@W1+b1)) (params inline); z2 = y@W2+b2; write z2; stats of z2 (9 ch)
__global__ void __launch_bounds__(256, 2) k_nodeY(const float* __restrict__ W1,
                                                  const float* __restrict__ b1,
                                                  const float* __restrict__ W2,
                                                  const float* __restrict__ b2,
                                                  const float* __restrict__ bn1_g,
                                                  const float* __restrict__ bn1_b, int l) {
    __shared__ float sW1[162], sW2[162], sb1[18], sb2[9], sP[36], racc[36];
    int t = threadIdx.x;
    if (t < 162) { sW1[t] = W1[t]; sW2[t] = W2[t]; }
    if (t < 18) sb1[t] = b1[t];
    if (t < 9)  sb2[t] = b2[t];
    if (t < 36) racc[t] = 0.f;
    compute_bn(g_stZ1 + l * 36, 18, 1.0 / (double)NN, bn1_g, bn1_b, sP);
    __syncthreads();
    float s[9], q[9];
    #pragma unroll
    for (int c = 0; c < 9; c++) { s[c] = 0.f; q[c] = 0.f; }
    int base = blockIdx.x * (256 * NZI) + t;
    #pragma unroll 1
    for (int i = 0; i < NZI; i++) {
        int n = base + i * 256;
        float4* bp = (float4*)(g_buf + (size_t)n * PS);
        float4 a = bp[0], b4 = bp[1], c4 = bp[2];
        float z[9] = {a.x, a.y, a.z, a.w, b4.x, b4.y, b4.z, b4.w, c4.x};
        float z2[9];
        #pragma unroll
        for (int c = 0; c < 9; c++) z2[c] = sb2[c];
        #pragma unroll
        for (int c = 0; c < 18; c++) {
            float z1 = sb1[c];
            #pragma unroll
            for (int j = 0; j < 9; j++) z1 = fmaf(z[j], sW1[j * 18 + c], z1);
            float y = fmaxf(fmaf(z1, sP[c], sP[18 + c]), 0.f);
            #pragma unroll
            for (int j = 0; j < 9; j++) z2[j] = fmaf(y, sW2[c * 9 + j], z2[j]);
        }
        bp[0] = make_float4(z2[0], z2[1], z2[2], z2[3]);
        bp[1] = make_float4(z2[4], z2[5], z2[6], z2[7]);
        bp[2] = make_float4(z2[8], 0.f, 0.f, 0.f);
        #pragma unroll
        for (int c = 0; c < 9; c++) {
            s[c] += z2[c];
            q[c] = fmaf(z2[c], z2[c], q[c]);
        }
    }
    stats_flush(s, q, 9, g_stZ2 + l * 36, racc);
}

// VN step A: vn_tmp = graphsum + vn (stored back into g_gs); stats of vn_tmp@vnW1+vnb1
__global__ void __launch_bounds__(256, 2) k_vnA(const float* __restrict__ W1,
                                                const float* __restrict__ b1, int l) {
    __shared__ float sW[162], sb[18], racc[36];
    int t = threadIdx.x;
    if (t < 162) sW[t] = W1[t];
    if (t < 18)  sb[t] = b1[t];
    if (t < 36)  racc[t] = 0.f;
    __syncthreads();
    int g = blockIdx.x * 256 + t;
    float4* gp = (float4*)(g_gs + (size_t)g * PS);
    const float4* vp = (const float4*)(g_vn + (size_t)g * PS);
    float4 a = gp[0], b4 = gp[1], c4 = gp[2];
    float4 va = vp[0], vb = vp[1], vc = vp[2];
    float vt[9] = {a.x + va.x, a.y + va.y, a.z + va.z, a.w + va.w,
                   b4.x + vb.x, b4.y + vb.y, b4.z + vb.z, b4.w + vb.w, c4.x + vc.x};
    gp[0] = make_float4(vt[0], vt[1], vt[2], vt[3]);
    gp[1] = make_float4(vt[4], vt[5], vt[6], vt[7]);
    gp[2] = make_float4(vt[8], 0.f, 0.f, 0.f);
    float s[18], q[18];
    #pragma unroll
    for (int c = 0; c < 18; c++) {
        float u = sb[c];
        #pragma unroll
        for (int j = 0; j < 9; j++) u = fmaf(vt[j], sW[j * 18 + c], u);
        s[c] = u; q[c] = u * u;
    }
    stats_flush(s, q, 18, g_stV1 + l * 36, racc);
}

// VN step B: t = relu(BN1(u1)) (inline params); u2 = t@vnW2+vnb2 -> g_gs; stats of u2
__global__ void __launch_bounds__(256, 2) k_vnB(const float* __restrict__ W1,
                                                const float* __restrict__ b1,
                                                const float* __restrict__ W2,
                                                const float* __restrict__ b2,
                                                const float* __restrict__ bn_g,
                                                const float* __restrict__ bn_b, int l) {
    __shared__ float sW1[162], sW2[162], sb1[18], sb2[9], sP[36], racc[36];
    int t = threadIdx.x;
    if (t < 162) { sW1[t] = W1[t]; sW2[t] = W2[t]; }
    if (t < 18) sb1[t] = b1[t];
    if (t < 9)  sb2[t] = b2[t];
    if (t < 36) racc[t] = 0.f;
    compute_bn(g_stV1 + l * 36, 18, 1.0 / (double)GG, bn_g, bn_b, sP);
    __syncthreads();
    int g = blockIdx.x * 256 + t;
    float4* gp = (float4*)(g_gs + (size_t)g * PS);
    float4 a = gp[0], b4 = gp[1], c4 = gp[2];
    float vt[9] = {a.x, a.y, a.z, a.w, b4.x, b4.y, b4.z, b4.w, c4.x};
    float u2[9];
    #pragma unroll
    for (int c = 0; c < 9; c++) u2[c] = sb2[c];
    #pragma unroll
    for (int c = 0; c < 18; c++) {
        float u = sb1[c];
        #pragma unroll
        for (int j = 0; j < 9; j++) u = fmaf(vt[j], sW1[j * 18 + c], u);
        float y = fmaxf(fmaf(u, sP[c], sP[18 + c]), 0.f);
        #pragma unroll
        for (int j = 0; j < 9; j++) u2[j] = fmaf(y, sW2[c * 9 + j], u2[j]);
    }
    gp[0] = make_float4(u2[0], u2[1], u2[2], u2[3]);
    gp[1] = make_float4(u2[4], u2[5], u2[6], u2[7]);
    gp[2] = make_float4(u2[8], 0.f, 0.f, 0.f);
    float s[9], q[9];
    #pragma unroll
    for (int c = 0; c < 9; c++) { s[c] = u2[c]; q[c] = u2[c] * u2[c]; }
    stats_flush(s, q, 9, g_stV2 + l * 36, racc);
}

// VN step C: vn += relu(BN2(u2)) (inline params); zero graph-sum buffer for next layer
__global__ void __launch_bounds__(256) k_vnC(const float* __restrict__ bn_g,
                                             const float* __restrict__ bn_b, int l) {
    __shared__ float sP[18];
    compute_bn(g_stV2 + l * 36, 9, 1.0 / (double)GG, bn_g, bn_b, sP);
    __syncthreads();
    int g = blockIdx.x * 256 + threadIdx.x;
    float4* gp = (float4*)(g_gs + (size_t)g * PS);
    float4* vp = (float4*)(g_vn + (size_t)g * PS);
    float4 a = gp[0], b4 = gp[1], c4 = gp[2];
    float u2[9] = {a.x, a.y, a.z, a.w, b4.x, b4.y, b4.z, b4.w, c4.x};
    float4 va = vp[0], vb = vp[1], vc = vp[2];
    float vo[9] = {va.x, va.y, va.z, va.w, vb.x, vb.y, vb.z, vb.w, vc.x};
    #pragma unroll
    for (int k = 0; k < 9; k++)
        vo[k] += fmaxf(fmaf(u2[k], sP[k], sP[9 + k]), 0.f);
    vp[0] = make_float4(vo[0], vo[1], vo[2], vo[3]);
    vp[1] = make_float4(vo[4], vo[5], vo[6], vo[7]);
    vp[2] = make_float4(vo[8], 0.f, 0.f, 0.f);
    float4 zz = make_float4(0.f, 0.f, 0.f, 0.f);
    gp[0] = zz; gp[1] = zz; gp[2] = zz;
}

// layer finish (l<2): h_new = relu(BNout(z2)) + h_in (inline params); h_in' = h_new + vn'[batch]
__global__ void __launch_bounds__(256) k_final_mid(const int* __restrict__ batch,
                                                   const float* __restrict__ bn_g,
                                                   const float* __restrict__ bn_b,
                                                   int l, int accumGS) {
    __shared__ float sP[18];
    compute_bn(g_stZ2 + l * 36, 9, 1.0 / (double)NN, bn_g, bn_b, sP);
    __syncthreads();
    int n = blockIdx.x * 256 + threadIdx.x;   // grid exactly covers NN
    float4* bp = (float4*)(g_buf + (size_t)n * PS);
    float4* hp = (float4*)(g_hin + (size_t)n * PS);
    float4 a = bp[0], b4 = bp[1], c4 = bp[2];
    float z2[9] = {a.x, a.y, a.z, a.w, b4.x, b4.y, b4.z, b4.w, c4.x};
    float4 ha = hp[0], hb = hp[1], hc = hp[2];
    float hi[9] = {ha.x, ha.y, ha.z, ha.w, hb.x, hb.y, hb.z, hb.w, hc.x};
    int g = __ldg(batch + n);
    const float4* vp = (const float4*)(g_vn + (size_t)g * PS);
    float4 va = vp[0], vb = vp[1], vc = vp[2];
    float vn9[9] = {va.x, va.y, va.z, va.w, vb.x, vb.y, vb.z, vb.w, vc.x};
    float hx[9];
    #pragma unroll
    for (int k = 0; k < 9; k++) {
        float zn = fmaxf(fmaf(z2[k], sP[k], sP[9 + k]), 0.f);
        hx[k] = zn + hi[k] + vn9[k];
    }
    hp[0] = make_float4(hx[0], hx[1], hx[2], hx[3]);
    hp[1] = make_float4(hx[4], hx[5], hx[6], hx[7]);
    hp[2] = make_float4(hx[8], 0.f, 0.f, 0.f);
    float4 zz = make_float4(0.f, 0.f, 0.f, 0.f);
    bp[0] = zz; bp[1] = zz; bp[2] = zz;
    if (accumGS) seg_atomic9(g, hx, g_gs);
}

// last layer finish: h = BNout(z2) + h_in (no relu, inline params); global sum
__global__ void __launch_bounds__(256, 2) k_final_last(const float* __restrict__ bn_g,
                                                       const float* __restrict__ bn_b, int l) {
    __shared__ float sP[18], racc[9];
    compute_bn(g_stZ2 + l * 36, 9, 1.0 / (double)NN, bn_g, bn_b, sP);
    if (threadIdx.x < 9) racc[threadIdx.x] = 0.f;
    __syncthreads();
    float hs[9];
    #pragma unroll
    for (int k = 0; k < 9; k++) hs[k] = 0.f;
    int base = blockIdx.x * (256 * NZI) + threadIdx.x;
    #pragma unroll 1
    for (int i = 0; i < NZI; i++) {
        int n = base + i * 256;
        const float4* bp = (const float4*)(g_buf + (size_t)n * PS);
        const float4* hp = (const float4*)(g_hin + (size_t)n * PS);
        float4 a = bp[0], b4 = bp[1], c4 = bp[2];
        float z2[9] = {a.x, a.y, a.z, a.w, b4.x, b4.y, b4.z, b4.w, c4.x};
        float4 ha = hp[0], hb = hp[1], hc = hp[2];
        float hi[9] = {ha.x, ha.y, ha.z, ha.w, hb.x, hb.y, hb.z, hb.w, hc.x};
        #pragma unroll
        for (int k = 0; k < 9; k++)
            hs[k] += fmaf(z2[k], sP[k], sP[9 + k]) + hi[k];
    }
    int lane = threadIdx.x & 31;
    #pragma unroll
    for (int k = 0; k < 9; k++) {
        float v = warp_sum(hs[k]);
        if (lane == 0) atomicAdd(&racc[k], v);
    }
    __syncthreads();
    if (threadIdx.x < 9) atomicAdd(&g_outacc[threadIdx.x], (double)racc[threadIdx.x]);
}

__global__ void k_out(float* __restrict__ out) {
    if (threadIdx.x < 9) out[threadIdx.x] = (float)g_outacc[threadIdx.x];
}

// ---------------- host ----------------
extern "C" void kernel_launch(void* const* d_in, const int* in_sizes, int n_in,
                              void* d_out, int out_size) {
    const float* atom_emb = (const float*)d_in[0];
    const float* bond_emb = (const float*)d_in[1];
    const float* eps_gin  = (const float*)d_in[2];
    const float* W1       = (const float*)d_in[3];
    const float* b1       = (const float*)d_in[4];
    const float* bn1_g    = (const float*)d_in[5];
    const float* bn1_b    = (const float*)d_in[6];
    const float* W2       = (const float*)d_in[7];
    const float* b2       = (const float*)d_in[8];
    const float* bno_g    = (const float*)d_in[9];
    const float* bno_b    = (const float*)d_in[10];
    const float* vnW1     = (const float*)d_in[11];
    const float* vnb1     = (const float*)d_in[12];
    const float* vnbn1_g  = (const float*)d_in[13];
    const float* vnbn1_b  = (const float*)d_in[14];
    const float* vnW2     = (const float*)d_in[15];
    const float* vnb2     = (const float*)d_in[16];
    const float* vnbn2_g  = (const float*)d_in[17];
    const float* vnbn2_b  = (const float*)d_in[18];
    const int*   x        = (const int*)d_in[19];
    const int*   eidx     = (const int*)d_in[20];
    const int*   eattr    = (const int*)d_in[21];
    const int*   batch    = (const int*)d_in[22];
    (void)in_sizes; (void)n_in; (void)out_size;

    k_init<<<(GG * PS + 255) / 256, 256>>>();
    k_atom<<<NB_N, 256>>>(atom_emb, x, batch);

    for (int l = 0; l < 3; l++) {
        k_edge<<<NB_E, 256>>>(bond_emb + l * 162, eidx, eidx + EE, eattr);
        k_nodeZ<<<NB_STAT, 256>>>(W1 + l * 162, b1 + l * 18, eps_gin + l, l);
        k_nodeY<<<NB_STAT, 256>>>(W1 + l * 162, b1 + l * 18, W2 + l * 162, b2 + l * 9,
                                  bn1_g + l * 18, bn1_b + l * 18, l);
        if (l < 2) {
            k_vnA<<<NB_G, 256>>>(vnW1 + l * 162, vnb1 + l * 18, l);
            k_vnB<<<NB_G, 256>>>(vnW1 + l * 162, vnb1 + l * 18, vnW2 + l * 162,
                                 vnb2 + l * 9, vnbn1_g + l * 18, vnbn1_b + l * 18, l);
            k_vnC<<<NB_G, 256>>>(vnbn2_g + l * 9, vnbn2_b + l * 9, l);
            k_final_mid<<<NB_N, 256>>>(batch, bno_g + l * 9, bno_b + l * 9, l,
                                       (l == 0) ? 1 : 0);
        } else {
            k_final_last<<<NB_STAT, 256>>>(bno_g + l * 9, bno_b + l * 9, l);
        }
    }
    k_out<<<1, 32>>>((float*)d_out);
}